// round 14
// baseline (speedup 1.0000x reference)
#include <cuda_runtime.h>
#include <cuda_fp16.h>
#include <cstdint>
#include <cstddef>

#define BB 32
#define NNODE 1024
#define DD 512

__device__ __half g_sch[(size_t)BB * NNODE * NNODE];   // fp16 sc
__device__ __half g_Ath[(size_t)BB * NNODE * NNODE];   // fp16 sc^T
__device__ __half g_P  [(size_t)BB * DD * NNODE];      // Y1/Y2 feat-major [b][feat][node]
__device__ __half g_Qh [(size_t)BB * NNODE * DD];      // H1, then H2 (fp16)
__device__ __half g_W1t[DD * NNODE];
__device__ __half g_W2t[DD * DD];
__device__ float  g_dis[BB * NNODE];

__device__ __forceinline__ uint32_t smem_u32(const void* p) {
    uint32_t a;
    asm("{ .reg .u64 t; cvta.to.shared.u64 t, %1; cvt.u32.u64 %0, t; }" : "=r"(a) : "l"(p));
    return a;
}
__device__ __forceinline__ void cp16(uint32_t s, const void* g) {
    asm volatile("cp.async.cg.shared.global [%0], [%1], 16;" :: "r"(s), "l"(g));
}
__device__ __forceinline__ void ldm_x4(uint32_t* r, uint32_t a) {
    asm volatile("ldmatrix.sync.aligned.m8n8.x4.shared.b16 {%0,%1,%2,%3}, [%4];"
        : "=r"(r[0]), "=r"(r[1]), "=r"(r[2]), "=r"(r[3]) : "r"(a));
}
__device__ __forceinline__ void ldm_x2(uint32_t& r0, uint32_t& r1, uint32_t a) {
    asm volatile("ldmatrix.sync.aligned.m8n8.x2.shared.b16 {%0,%1}, [%2];"
        : "=r"(r0), "=r"(r1) : "r"(a));
}

// 128x128 tile, rows of 32 fp16 (64B) padded to 80B (20 banks, conflict-free)
static constexpr int ROW_B   = 80;
static constexpr int ATILE   = 128 * ROW_B;         // 10240 B
static constexpr int STG     = 2 * ATILE;           // 20480 B per stage
static constexpr int NSTAGE  = 3;
static constexpr int SMEM_BYTES = NSTAGE * STG;     // 61440 B (opt-in)

// ---------------------------------------------------------------------------
// fp16 mma.sync GEMM: CTA tile 128x128, K-chunk 32, 8 warps (2x4), warp 64x32,
// ldmatrix frags, 3-stage cp.async ring, ONE sync per chunk.
// C[m,n] = acc * (COLSCALE ? dis[n] : dis[m]) (+bias[n]) (relu); fp16/fp32 out.
// ---------------------------------------------------------------------------
template<bool COLSCALE, bool RELU, bool HASBIAS, bool OUTHALF>
__global__ __launch_bounds__(256, 2)
void hgemm(const __half* __restrict__ Ap, const __half* __restrict__ Bp,
           void* __restrict__ Cpv, const float* __restrict__ disv,
           const float* __restrict__ bias,
           int K, int lda, int ldb, int ldc,
           size_t sA, size_t sB, size_t sC, size_t sD)
{
    extern __shared__ char smem[];
    const uint32_t sbase = smem_u32(smem);
    const int tid = threadIdx.x;
    const int wid = tid >> 5;
    const int lane = tid & 31;
    const int wm = wid >> 2;
    const int wn = wid & 3;
    const int lrow = lane >> 2;
    const int lcol = lane & 3;
    const int bz = blockIdx.z;
    const int m0 = blockIdx.y * 128;
    const int n0 = blockIdx.x * 128;

    Ap += (size_t)bz * sA;
    Bp += (size_t)bz * sB;
    disv += (size_t)bz * sD;
    if (OUTHALF) Cpv = (void*)((__half*)Cpv + (size_t)bz * sC);
    else         Cpv = (void*)((float*)Cpv + (size_t)bz * sC);

    const int S = K / 32;

    auto load_stage = [&](int k0, uint32_t soff) {
        #pragma unroll
        for (int p = 0; p < 2; p++) {
            int id = tid + 256 * p;
            int row = id >> 2, c = id & 3;
            cp16(sbase + soff + (uint32_t)(row * ROW_B + c * 16),
                 Ap + (size_t)(m0 + row) * lda + k0 + c * 8);
            cp16(sbase + soff + ATILE + (uint32_t)(row * ROW_B + c * 16),
                 Bp + (size_t)(n0 + row) * ldb + k0 + c * 8);
        }
        asm volatile("cp.async.commit_group;" ::: "memory");
    };

    load_stage(0, 0);
    if (S > 1) load_stage(32, STG);

    float acc[4][4][4];
    #pragma unroll
    for (int mi = 0; mi < 4; mi++)
        #pragma unroll
        for (int ni = 0; ni < 4; ni++)
            #pragma unroll
            for (int q = 0; q < 4; q++) acc[mi][ni][q] = 0.f;

    const uint32_t aRowBase = (uint32_t)(wm * 64 + (lane & 15)) * ROW_B
                              + ((uint32_t)(lane >> 4) & 1u) * 16u;
    const uint32_t bRowBase = (uint32_t)(wn * 32 + (lane & 7)) * ROW_B
                              + ((uint32_t)(lane >> 3) & 1u) * 16u;

    for (int s = 0; s < S; s++) {
        if (s + 1 < S) asm volatile("cp.async.wait_group 1;" ::: "memory");
        else           asm volatile("cp.async.wait_group 0;" ::: "memory");
        __syncthreads();            // single barrier per chunk

        const uint32_t aB = sbase + (uint32_t)(s % NSTAGE) * STG;
        const uint32_t bB = aB + ATILE;

        #pragma unroll
        for (int kk = 0; kk < 2; kk++) {
            uint32_t a[4][4];
            #pragma unroll
            for (int mi = 0; mi < 4; mi++)
                ldm_x4(a[mi], aB + aRowBase + (uint32_t)(mi * 16) * ROW_B + kk * 32);
            #pragma unroll
            for (int ni = 0; ni < 4; ni++) {
                uint32_t b0, b1;
                ldm_x2(b0, b1, bB + bRowBase + (uint32_t)(ni * 8) * ROW_B + kk * 32);
                #pragma unroll
                for (int mi = 0; mi < 4; mi++) {
                    asm volatile(
                        "mma.sync.aligned.m16n8k16.row.col.f32.f16.f16.f32 "
                        "{%0,%1,%2,%3}, {%4,%5,%6,%7}, {%8,%9}, {%0,%1,%2,%3};"
                        : "+f"(acc[mi][ni][0]), "+f"(acc[mi][ni][1]),
                          "+f"(acc[mi][ni][2]), "+f"(acc[mi][ni][3])
                        : "r"(a[mi][0]), "r"(a[mi][1]), "r"(a[mi][2]), "r"(a[mi][3]),
                          "r"(b0), "r"(b1));
                }
            }
        }
        if (s + 2 < S) load_stage((s + 2) * 32, (uint32_t)((s + 2) % NSTAGE) * STG);
    }

    #pragma unroll
    for (int mi = 0; mi < 4; mi++) {
        const int ml = m0 + wm * 64 + mi * 16 + lrow;
        float d0 = 1.f, d1 = 1.f;
        if (!COLSCALE) { d0 = disv[ml]; d1 = disv[ml + 8]; }
        #pragma unroll
        for (int ni = 0; ni < 4; ni++) {
            const int n = n0 + wn * 32 + ni * 8 + 2 * lcol;
            float cs0 = 1.f, cs1 = 1.f;
            if (COLSCALE) { cs0 = disv[n]; cs1 = disv[n + 1]; }
            float bx = 0.f, by = 0.f;
            if (HASBIAS) { bx = bias[n]; by = bias[n + 1]; }
            float v0, v1, v2, v3;
            if (COLSCALE) {
                v0 = acc[mi][ni][0] * cs0 + bx;
                v1 = acc[mi][ni][1] * cs1 + by;
                v2 = acc[mi][ni][2] * cs0 + bx;
                v3 = acc[mi][ni][3] * cs1 + by;
            } else {
                v0 = acc[mi][ni][0] * d0 + bx;
                v1 = acc[mi][ni][1] * d0 + by;
                v2 = acc[mi][ni][2] * d1 + bx;
                v3 = acc[mi][ni][3] * d1 + by;
            }
            if (RELU) {
                v0 = fmaxf(v0, 0.f); v1 = fmaxf(v1, 0.f);
                v2 = fmaxf(v2, 0.f); v3 = fmaxf(v3, 0.f);
            }
            if (OUTHALF) {
                __half* C = (__half*)Cpv;
                *(__half2*)&C[(size_t)ml * ldc + n] = __floats2half2_rn(v0, v1);
                *(__half2*)&C[(size_t)(ml + 8) * ldc + n] = __floats2half2_rn(v2, v3);
            } else {
                float* C = (float*)Cpv;
                *(float2*)&C[(size_t)ml * ldc + n] = make_float2(v0, v1);
                *(float2*)&C[(size_t)(ml + 8) * ldc + n] = make_float2(v2, v3);
            }
        }
    }
}

// ---------------------------------------------------------------------------
__global__ void zero2_kernel(float* a, int na, float* c, int nc)
{
    int i = blockIdx.x * 256 + threadIdx.x;
    if (i < na) a[i] = 0.f;
    if (i < nc) c[i] = 0.f;
}

__global__ void sc_prep(const float* __restrict__ sc, __half* __restrict__ sch,
                        __half* __restrict__ Ath, float* __restrict__ dacc)
{
    __shared__ float t[32][33];
    __shared__ float cs[32];
    const size_t zoff = (size_t)blockIdx.z * NNODE * NNODE;
    const int r0 = blockIdx.y * 32, c0 = blockIdx.x * 32;
    const int tx = threadIdx.x, ty = threadIdx.y;
    float v[4];
    #pragma unroll
    for (int q = 0; q < 4; q++) {
        size_t idx = zoff + (size_t)(r0 + ty + q * 8) * NNODE + c0 + tx;
        v[q] = sc[idx];
        sch[idx] = __float2half_rn(v[q]);
        t[ty + q * 8][tx] = v[q];
    }
    if (ty == 0) cs[tx] = 0.f;
    __syncthreads();
    atomicAdd(&cs[tx], (v[0] + v[1]) + (v[2] + v[3]));
    #pragma unroll
    for (int q = 0; q < 4; q++)
        Ath[zoff + (size_t)(c0 + ty + q * 8) * NNODE + r0 + tx] =
            __float2half_rn(t[tx][ty + q * 8]);
    __syncthreads();
    if (ty == 0) atomicAdd(&dacc[(size_t)blockIdx.z * NNODE + c0 + tx], cs[tx]);
}

__global__ void rsqrt_fin(float* __restrict__ dis)
{
    int i = blockIdx.x * 256 + threadIdx.x;
    float s = dis[i];
    dis[i] = (s > 0.f) ? rsqrtf(s) : 0.f;
}

__global__ void w_prep(const float* __restrict__ src, __half* __restrict__ dst,
                       int R, int C)
{
    __shared__ float t[32][33];
    const int r0 = blockIdx.y * 32, c0 = blockIdx.x * 32;
    const int tx = threadIdx.x, ty = threadIdx.y;
    #pragma unroll
    for (int q = 0; q < 4; q++)
        t[ty + q * 8][tx] = src[(size_t)(r0 + ty + q * 8) * C + c0 + tx];
    __syncthreads();
    #pragma unroll
    for (int q = 0; q < 4; q++)
        dst[(size_t)(c0 + ty + q * 8) * R + r0 + tx] = __float2half_rn(t[tx][ty + q * 8]);
}

// ---------------------------------------------------------------------------
// Fused LayerNorm + mean-pool over fp16 H2: zp[b,:] += LN(Q[b,i,:]) / 1024
// ---------------------------------------------------------------------------
__global__ void ln_pool_kernel(const __half* __restrict__ Q,
                               const float* __restrict__ g,
                               const float* __restrict__ bta,
                               float* __restrict__ zp)
{
    const int b = blockIdx.y;
    const int chunk = blockIdx.x;
    const int wid = threadIdx.x >> 5;
    const int lane = threadIdx.x & 31;

    float4 g4[4], b4[4];
    #pragma unroll
    for (int q = 0; q < 4; q++) {
        g4[q] = ((const float4*)g)[lane + 32 * q];
        b4[q] = ((const float4*)bta)[lane + 32 * q];
    }
    float4 acc[4];
    #pragma unroll
    for (int q = 0; q < 4; q++) acc[q] = make_float4(0.f, 0.f, 0.f, 0.f);

    const __half* base = Q + ((size_t)b * NNODE + chunk * 128 + wid * 32) * DD;
    for (int r = 0; r < 32; r++) {
        const uint2* row = (const uint2*)(base + (size_t)r * DD);
        float4 v[4];
        float s = 0.f;
        #pragma unroll
        for (int q = 0; q < 4; q++) {
            uint2 raw = row[lane + 32 * q];
            float2 lo = __half22float2(*(const __half2*)&raw.x);
            float2 hi = __half22float2(*(const __half2*)&raw.y);
            v[q] = make_float4(lo.x, lo.y, hi.x, hi.y);
            s += (v[q].x + v[q].y) + (v[q].z + v[q].w);
        }
        #pragma unroll
        for (int o = 16; o; o >>= 1) s += __shfl_xor_sync(0xffffffffu, s, o);
        const float mu = s * (1.f / DD);
        float s2 = 0.f;
        #pragma unroll
        for (int q = 0; q < 4; q++) {
            float dx = v[q].x - mu, dy = v[q].y - mu;
            float dz = v[q].z - mu, dw = v[q].w - mu;
            s2 += (dx * dx + dy * dy) + (dz * dz + dw * dw);
        }
        #pragma unroll
        for (int o = 16; o; o >>= 1) s2 += __shfl_xor_sync(0xffffffffu, s2, o);
        const float rinv = rsqrtf(s2 * (1.f / DD) + 1e-5f);
        #pragma unroll
        for (int q = 0; q < 4; q++) {
            acc[q].x += (v[q].x - mu) * rinv * g4[q].x + b4[q].x;
            acc[q].y += (v[q].y - mu) * rinv * g4[q].y + b4[q].y;
            acc[q].z += (v[q].z - mu) * rinv * g4[q].z + b4[q].z;
            acc[q].w += (v[q].w - mu) * rinv * g4[q].w + b4[q].w;
        }
    }
    const float sc = 1.f / NNODE;
    float* zb = zp + b * DD;
    #pragma unroll
    for (int q = 0; q < 4; q++) {
        int f = 4 * (lane + 32 * q);
        atomicAdd(&zb[f + 0], acc[q].x * sc);
        atomicAdd(&zb[f + 1], acc[q].y * sc);
        atomicAdd(&zb[f + 2], acc[q].z * sc);
        atomicAdd(&zb[f + 3], acc[q].w * sc);
    }
}

// ---------------------------------------------------------------------------
__device__ __forceinline__ float block_sum128(float v, float* red, int t)
{
    #pragma unroll
    for (int off = 16; off; off >>= 1) v += __shfl_down_sync(0xffffffffu, v, off);
    if ((t & 31) == 0) red[t >> 5] = v;
    __syncthreads();
    float s = red[0] + red[1] + red[2] + red[3];
    __syncthreads();
    return s;
}

__global__ void classifier_kernel(const float* __restrict__ zp,
                                  const float* __restrict__ Wc1, const float* __restrict__ bc1,
                                  const float* __restrict__ g1,  const float* __restrict__ t1,
                                  const float* __restrict__ Wc2, const float* __restrict__ bc2,
                                  const float* __restrict__ g2,  const float* __restrict__ t2,
                                  const float* __restrict__ Wc3, const float* __restrict__ bc3,
                                  float* __restrict__ logits)
{
    const int b = blockIdx.x;
    const int t = threadIdx.x;
    __shared__ float z[DD];
    __shared__ float h1[128];
    __shared__ float h2[64];
    __shared__ float red[4];

    #pragma unroll
    for (int i = t; i < DD; i += 128) z[i] = zp[b * DD + i];
    __syncthreads();

    float a1 = bc1[t];
    #pragma unroll 8
    for (int k = 0; k < DD; k++) a1 += z[k] * Wc1[k * 128 + t];
    float mu = block_sum128(a1, red, t) * (1.f / 128.f);
    float d0 = a1 - mu;
    float var = block_sum128(d0 * d0, red, t) * (1.f / 128.f);
    h1[t] = fmaxf(d0 * rsqrtf(var + 1e-5f) * g1[t] + t1[t], 0.f);
    __syncthreads();

    float a2 = 0.f;
    if (t < 64) {
        a2 = bc2[t];
        #pragma unroll 8
        for (int k = 0; k < 128; k++) a2 += h1[k] * Wc2[k * 64 + t];
    }
    float c1 = (t < 64) ? a2 : 0.f;
    float mu2 = block_sum128(c1, red, t) * (1.f / 64.f);
    float d2 = a2 - mu2;
    float c2v = (t < 64) ? d2 * d2 : 0.f;
    float var2 = block_sum128(c2v, red, t) * (1.f / 64.f);
    if (t < 64)
        h2[t] = fmaxf(d2 * rsqrtf(var2 + 1e-5f) * g2[t] + t2[t], 0.f);
    __syncthreads();

    if (t < 4) {
        float a3 = bc3[t];
        #pragma unroll
        for (int k = 0; k < 64; k++) a3 += h2[k] * Wc3[k * 4 + t];
        logits[b * 4 + t] = a3;
    }
}

// ---------------------------------------------------------------------------
extern "C" void kernel_launch(void* const* d_in, const int* in_sizes, int n_in,
                              void* d_out, int out_size)
{
    const float* sc  = (const float*)d_in[0];
    const float* W1  = (const float*)d_in[1];
    const float* b1  = (const float*)d_in[2];
    const float* W2  = (const float*)d_in[3];
    const float* b2  = (const float*)d_in[4];
    const float* lng = (const float*)d_in[5];
    const float* lnb = (const float*)d_in[6];
    const float* Wc1 = (const float*)d_in[7];
    const float* bc1 = (const float*)d_in[8];
    const float* g1  = (const float*)d_in[9];
    const float* t1  = (const float*)d_in[10];
    const float* Wc2 = (const float*)d_in[11];
    const float* bc2 = (const float*)d_in[12];
    const float* g2  = (const float*)d_in[13];
    const float* t2  = (const float*)d_in[14];
    const float* Wc3 = (const float*)d_in[15];
    const float* bc3 = (const float*)d_in[16];
    float* out = (float*)d_out;
    float* zp = out + BB * 4;

    __half *sch, *Ath, *P, *Qh, *W1t, *W2t;
    float *dis;
    cudaGetSymbolAddress((void**)&sch, g_sch);
    cudaGetSymbolAddress((void**)&Ath, g_Ath);
    cudaGetSymbolAddress((void**)&P,   g_P);
    cudaGetSymbolAddress((void**)&Qh,  g_Qh);
    cudaGetSymbolAddress((void**)&W1t, g_W1t);
    cudaGetSymbolAddress((void**)&W2t, g_W2t);
    cudaGetSymbolAddress((void**)&dis, g_dis);

    cudaFuncSetAttribute(hgemm<true,  false, false, true >,
                         cudaFuncAttributeMaxDynamicSharedMemorySize, SMEM_BYTES);
    cudaFuncSetAttribute(hgemm<false, true,  true,  true >,
                         cudaFuncAttributeMaxDynamicSharedMemorySize, SMEM_BYTES);
    cudaFuncSetAttribute(hgemm<false, false, true,  true >,
                         cudaFuncAttributeMaxDynamicSharedMemorySize, SMEM_BYTES);

    // zero zp (output region) + dis accumulator — every replay, in-graph
    zero2_kernel<<<128, 256>>>(zp, BB * DD, dis, BB * NNODE);

    dim3 tb(32, 8);
    sc_prep<<<dim3(32, 32, BB), tb>>>(sc, sch, Ath, dis);
    rsqrt_fin<<<BB * NNODE / 256, 256>>>(dis);
    w_prep<<<dim3(DD / 32, NNODE / 32), tb>>>(W1, W1t, NNODE, DD);
    w_prep<<<dim3(DD / 32, DD / 32), tb>>>(W2, W2t, DD, DD);

    // G1: P[b][f][j] = h(dis[b,j] * sum_k W1t[f,k]*sch[b][j,k])   (col-scale)
    hgemm<true, false, false, true><<<dim3(NNODE / 128, DD / 128, BB), 256, SMEM_BYTES>>>(
        W1t, sch, P, dis, nullptr, NNODE, NNODE, NNODE, NNODE,
        0, (size_t)NNODE * NNODE, (size_t)DD * NNODE, NNODE);

    // G2: Qh[b][i][n] = h(relu(dis[b,i]*sum_j Ath[b][i,j]*P[b][n,j] + b1[n]))
    hgemm<false, true, true, true><<<dim3(DD / 128, NNODE / 128, BB), 256, SMEM_BYTES>>>(
        Ath, P, Qh, dis, b1, NNODE, NNODE, NNODE, DD,
        (size_t)NNODE * NNODE, (size_t)DD * NNODE, (size_t)NNODE * DD, NNODE);

    // G3: P[b][f][j] = h(dis[b,j] * sum_k W2t[f,k]*Qh[b][j,k])    (col-scale)
    hgemm<true, false, false, true><<<dim3(NNODE / 128, DD / 128, BB), 256, SMEM_BYTES>>>(
        W2t, Qh, P, dis, nullptr, DD, DD, DD, NNODE,
        0, (size_t)NNODE * DD, (size_t)DD * NNODE, NNODE);

    // G4: Qh[b][i][n] = h(dis[b,i]*sum_j Ath[b][i,j]*P[b][n,j] + b2[n])  (fp16 H2)
    hgemm<false, false, true, true><<<dim3(DD / 128, NNODE / 128, BB), 256, SMEM_BYTES>>>(
        Ath, P, Qh, dis, b2, NNODE, NNODE, NNODE, DD,
        (size_t)NNODE * NNODE, (size_t)DD * NNODE, (size_t)NNODE * DD, NNODE);

    // fused LN + mean-pool over fp16 H2 -> zp, then classifier -> out[0:128)
    ln_pool_kernel<<<dim3(8, BB), 128>>>(Qh, lng, lnb, zp);
    classifier_kernel<<<BB, 128>>>(zp, Wc1, bc1, g1, t1,
                                   Wc2, bc2, g2, t2, Wc3, bc3, out);
}

// round 15
// speedup vs baseline: 1.0159x; 1.0159x over previous
#include <cuda_runtime.h>
#include <cuda_fp16.h>
#include <cstdint>
#include <cstddef>

#define BB 32
#define NNODE 1024
#define DD 512

__device__ __half g_Ath[(size_t)BB * NNODE * NNODE];   // fp16 sc^T (only copy of sc)
__device__ __half g_P  [(size_t)BB * DD * NNODE];      // Y1/Y2 feat-major [b][feat][node]
__device__ __half g_Qh [(size_t)BB * NNODE * DD];      // H1, then H2 (fp16)
__device__ __half g_W1t[DD * NNODE];
__device__ __half g_W2t[DD * DD];
__device__ float  g_dis[BB * NNODE];

__device__ __forceinline__ uint32_t smem_u32(const void* p) {
    uint32_t a;
    asm("{ .reg .u64 t; cvta.to.shared.u64 t, %1; cvt.u32.u64 %0, t; }" : "=r"(a) : "l"(p));
    return a;
}
__device__ __forceinline__ void cp16(uint32_t s, const void* g) {
    asm volatile("cp.async.cg.shared.global [%0], [%1], 16;" :: "r"(s), "l"(g));
}
__device__ __forceinline__ void ldm_x4(uint32_t* r, uint32_t a) {
    asm volatile("ldmatrix.sync.aligned.m8n8.x4.shared.b16 {%0,%1,%2,%3}, [%4];"
        : "=r"(r[0]), "=r"(r[1]), "=r"(r[2]), "=r"(r[3]) : "r"(a));
}
__device__ __forceinline__ void ldm_x2(uint32_t& r0, uint32_t& r1, uint32_t a) {
    asm volatile("ldmatrix.sync.aligned.m8n8.x2.shared.b16 {%0,%1}, [%2];"
        : "=r"(r0), "=r"(r1) : "r"(a));
}
__device__ __forceinline__ void ldm_x2_t(uint32_t& r0, uint32_t& r1, uint32_t a) {
    asm volatile("ldmatrix.sync.aligned.m8n8.x2.trans.shared.b16 {%0,%1}, [%2];"
        : "=r"(r0), "=r"(r1) : "r"(a));
}

// A tile (and n-major B): 128 rows x 32 fp16 (64B) padded to 80B.
// k-major B (BTRANS): 32 k-rows x 128 fp16 (256B) padded to 272B (bank-rotating).
static constexpr int ROW_B   = 80;
static constexpr int KROW_B  = 272;
static constexpr int ATILE   = 128 * ROW_B;         // 10240 B
static constexpr int STG     = 2 * ATILE;           // 20480 B per stage (covers both B kinds)
static constexpr int NSTAGE  = 3;
static constexpr int SMEM_BYTES = NSTAGE * STG;     // 61440 B (opt-in)

// ---------------------------------------------------------------------------
// fp16 mma.sync GEMM: CTA tile 128x128, K-chunk 32, 8 warps (2x4), warp 64x32,
// ldmatrix frags, 3-stage cp.async ring, ONE sync per chunk.
// BTRANS=false: B source row-major [N][K]. true: [K][N] (k-major, ldmatrix.trans).
// C[m,n] = acc * (COLSCALE ? dis[n] : dis[m]) (+bias[n]) (relu); fp16/fp32 out.
// ---------------------------------------------------------------------------
template<bool BTRANS, bool COLSCALE, bool RELU, bool HASBIAS, bool OUTHALF>
__global__ __launch_bounds__(256, 2)
void hgemm(const __half* __restrict__ Ap, const __half* __restrict__ Bp,
           void* __restrict__ Cpv, const float* __restrict__ disv,
           const float* __restrict__ bias,
           int K, int lda, int ldb, int ldc,
           size_t sA, size_t sB, size_t sC, size_t sD)
{
    extern __shared__ char smem[];
    const uint32_t sbase = smem_u32(smem);
    const int tid = threadIdx.x;
    const int wid = tid >> 5;
    const int lane = tid & 31;
    const int wm = wid >> 2;
    const int wn = wid & 3;
    const int lrow = lane >> 2;
    const int lcol = lane & 3;
    const int bz = blockIdx.z;
    const int m0 = blockIdx.y * 128;
    const int n0 = blockIdx.x * 128;

    Ap += (size_t)bz * sA;
    Bp += (size_t)bz * sB;
    disv += (size_t)bz * sD;
    if (OUTHALF) Cpv = (void*)((__half*)Cpv + (size_t)bz * sC);
    else         Cpv = (void*)((float*)Cpv + (size_t)bz * sC);

    const int S = K / 32;

    auto load_stage = [&](int k0, uint32_t soff) {
        #pragma unroll
        for (int p = 0; p < 2; p++) {
            int id = tid + 256 * p;
            {   // A: 128 rows x 32k
                int row = id >> 2, c = id & 3;
                cp16(sbase + soff + (uint32_t)(row * ROW_B + c * 16),
                     Ap + (size_t)(m0 + row) * lda + k0 + c * 8);
            }
            if (!BTRANS) {
                int row = id >> 2, c = id & 3;
                cp16(sbase + soff + ATILE + (uint32_t)(row * ROW_B + c * 16),
                     Bp + (size_t)(n0 + row) * ldb + k0 + c * 8);
            } else {
                int krow = id >> 4, c = id & 15;
                cp16(sbase + soff + ATILE + (uint32_t)(krow * KROW_B + c * 16),
                     Bp + (size_t)(k0 + krow) * ldb + n0 + c * 8);
            }
        }
        asm volatile("cp.async.commit_group;" ::: "memory");
    };

    load_stage(0, 0);
    if (S > 1) load_stage(32, STG);

    float acc[4][4][4];
    #pragma unroll
    for (int mi = 0; mi < 4; mi++)
        #pragma unroll
        for (int ni = 0; ni < 4; ni++)
            #pragma unroll
            for (int q = 0; q < 4; q++) acc[mi][ni][q] = 0.f;

    const uint32_t aRowBase = (uint32_t)(wm * 64 + (lane & 15)) * ROW_B
                              + ((uint32_t)(lane >> 4) & 1u) * 16u;
    const uint32_t bRowBase = (uint32_t)(wn * 32 + (lane & 7)) * ROW_B
                              + ((uint32_t)(lane >> 3) & 1u) * 16u;
    const uint32_t bTrBase  = (uint32_t)(lane & 15) * KROW_B
                              + (uint32_t)(wn * 32) * 2u;

    for (int s = 0; s < S; s++) {
        if (s + 1 < S) asm volatile("cp.async.wait_group 1;" ::: "memory");
        else           asm volatile("cp.async.wait_group 0;" ::: "memory");
        __syncthreads();            // single barrier per chunk

        const uint32_t aB = sbase + (uint32_t)(s % NSTAGE) * STG;
        const uint32_t bB = aB + ATILE;

        #pragma unroll
        for (int kk = 0; kk < 2; kk++) {
            uint32_t a[4][4];
            #pragma unroll
            for (int mi = 0; mi < 4; mi++)
                ldm_x4(a[mi], aB + aRowBase + (uint32_t)(mi * 16) * ROW_B + kk * 32);
            #pragma unroll
            for (int ni = 0; ni < 4; ni++) {
                uint32_t b0, b1;
                if (!BTRANS)
                    ldm_x2(b0, b1, bB + bRowBase + (uint32_t)(ni * 8) * ROW_B + kk * 32);
                else
                    ldm_x2_t(b0, b1, bB + bTrBase + (uint32_t)(kk * 16) * KROW_B
                                        + (uint32_t)(ni * 8) * 2u);
                #pragma unroll
                for (int mi = 0; mi < 4; mi++) {
                    asm volatile(
                        "mma.sync.aligned.m16n8k16.row.col.f32.f16.f16.f32 "
                        "{%0,%1,%2,%3}, {%4,%5,%6,%7}, {%8,%9}, {%0,%1,%2,%3};"
                        : "+f"(acc[mi][ni][0]), "+f"(acc[mi][ni][1]),
                          "+f"(acc[mi][ni][2]), "+f"(acc[mi][ni][3])
                        : "r"(a[mi][0]), "r"(a[mi][1]), "r"(a[mi][2]), "r"(a[mi][3]),
                          "r"(b0), "r"(b1));
                }
            }
        }
        if (s + 2 < S) load_stage((s + 2) * 32, (uint32_t)((s + 2) % NSTAGE) * STG);
    }

    #pragma unroll
    for (int mi = 0; mi < 4; mi++) {
        const int ml = m0 + wm * 64 + mi * 16 + lrow;
        float d0 = 1.f, d1 = 1.f;
        if (!COLSCALE) { d0 = disv[ml]; d1 = disv[ml + 8]; }
        #pragma unroll
        for (int ni = 0; ni < 4; ni++) {
            const int n = n0 + wn * 32 + ni * 8 + 2 * lcol;
            float cs0 = 1.f, cs1 = 1.f;
            if (COLSCALE) { cs0 = disv[n]; cs1 = disv[n + 1]; }
            float bx = 0.f, by = 0.f;
            if (HASBIAS) { bx = bias[n]; by = bias[n + 1]; }
            float v0, v1, v2, v3;
            if (COLSCALE) {
                v0 = acc[mi][ni][0] * cs0 + bx;
                v1 = acc[mi][ni][1] * cs1 + by;
                v2 = acc[mi][ni][2] * cs0 + bx;
                v3 = acc[mi][ni][3] * cs1 + by;
            } else {
                v0 = acc[mi][ni][0] * d0 + bx;
                v1 = acc[mi][ni][1] * d0 + by;
                v2 = acc[mi][ni][2] * d1 + bx;
                v3 = acc[mi][ni][3] * d1 + by;
            }
            if (RELU) {
                v0 = fmaxf(v0, 0.f); v1 = fmaxf(v1, 0.f);
                v2 = fmaxf(v2, 0.f); v3 = fmaxf(v3, 0.f);
            }
            if (OUTHALF) {
                __half* C = (__half*)Cpv;
                *(__half2*)&C[(size_t)ml * ldc + n] = __floats2half2_rn(v0, v1);
                *(__half2*)&C[(size_t)(ml + 8) * ldc + n] = __floats2half2_rn(v2, v3);
            } else {
                float* C = (float*)Cpv;
                *(float2*)&C[(size_t)ml * ldc + n] = make_float2(v0, v1);
                *(float2*)&C[(size_t)(ml + 8) * ldc + n] = make_float2(v2, v3);
            }
        }
    }
}

// ---------------------------------------------------------------------------
__global__ void zero2_kernel(float* a, int na, float* c, int nc)
{
    int i = blockIdx.x * 256 + threadIdx.x;
    if (i < na) a[i] = 0.f;
    if (i < nc) c[i] = 0.f;
}

// one pass over sc: fp16 transpose (only) + degree column sums
__global__ void sc_prep(const float* __restrict__ sc,
                        __half* __restrict__ Ath, float* __restrict__ dacc)
{
    __shared__ float t[32][33];
    __shared__ float cs[32];
    const size_t zoff = (size_t)blockIdx.z * NNODE * NNODE;
    const int r0 = blockIdx.y * 32, c0 = blockIdx.x * 32;
    const int tx = threadIdx.x, ty = threadIdx.y;
    float v[4];
    #pragma unroll
    for (int q = 0; q < 4; q++) {
        v[q] = sc[zoff + (size_t)(r0 + ty + q * 8) * NNODE + c0 + tx];
        t[ty + q * 8][tx] = v[q];
    }
    if (ty == 0) cs[tx] = 0.f;
    __syncthreads();
    atomicAdd(&cs[tx], (v[0] + v[1]) + (v[2] + v[3]));
    #pragma unroll
    for (int q = 0; q < 4; q++)
        Ath[zoff + (size_t)(c0 + ty + q * 8) * NNODE + r0 + tx] =
            __float2half_rn(t[tx][ty + q * 8]);
    __syncthreads();
    if (ty == 0) atomicAdd(&dacc[(size_t)blockIdx.z * NNODE + c0 + tx], cs[tx]);
}

__global__ void rsqrt_fin(float* __restrict__ dis)
{
    int i = blockIdx.x * 256 + threadIdx.x;
    float s = dis[i];
    dis[i] = (s > 0.f) ? rsqrtf(s) : 0.f;
}

__global__ void w_prep(const float* __restrict__ src, __half* __restrict__ dst,
                       int R, int C)
{
    __shared__ float t[32][33];
    const int r0 = blockIdx.y * 32, c0 = blockIdx.x * 32;
    const int tx = threadIdx.x, ty = threadIdx.y;
    #pragma unroll
    for (int q = 0; q < 4; q++)
        t[ty + q * 8][tx] = src[(size_t)(r0 + ty + q * 8) * C + c0 + tx];
    __syncthreads();
    #pragma unroll
    for (int q = 0; q < 4; q++)
        dst[(size_t)(c0 + ty + q * 8) * R + r0 + tx] = __float2half_rn(t[tx][ty + q * 8]);
}

// ---------------------------------------------------------------------------
// Fused LayerNorm + mean-pool over fp16 H2: zp[b,:] += LN(Q[b,i,:]) / 1024
// ---------------------------------------------------------------------------
__global__ void ln_pool_kernel(const __half* __restrict__ Q,
                               const float* __restrict__ g,
                               const float* __restrict__ bta,
                               float* __restrict__ zp)
{
    const int b = blockIdx.y;
    const int chunk = blockIdx.x;
    const int wid = threadIdx.x >> 5;
    const int lane = threadIdx.x & 31;

    float4 g4[4], b4[4];
    #pragma unroll
    for (int q = 0; q < 4; q++) {
        g4[q] = ((const float4*)g)[lane + 32 * q];
        b4[q] = ((const float4*)bta)[lane + 32 * q];
    }
    float4 acc[4];
    #pragma unroll
    for (int q = 0; q < 4; q++) acc[q] = make_float4(0.f, 0.f, 0.f, 0.f);

    const __half* base = Q + ((size_t)b * NNODE + chunk * 128 + wid * 32) * DD;
    for (int r = 0; r < 32; r++) {
        const uint2* row = (const uint2*)(base + (size_t)r * DD);
        float4 v[4];
        float s = 0.f;
        #pragma unroll
        for (int q = 0; q < 4; q++) {
            uint2 raw = row[lane + 32 * q];
            float2 lo = __half22float2(*(const __half2*)&raw.x);
            float2 hi = __half22float2(*(const __half2*)&raw.y);
            v[q] = make_float4(lo.x, lo.y, hi.x, hi.y);
            s += (v[q].x + v[q].y) + (v[q].z + v[q].w);
        }
        #pragma unroll
        for (int o = 16; o; o >>= 1) s += __shfl_xor_sync(0xffffffffu, s, o);
        const float mu = s * (1.f / DD);
        float s2 = 0.f;
        #pragma unroll
        for (int q = 0; q < 4; q++) {
            float dx = v[q].x - mu, dy = v[q].y - mu;
            float dz = v[q].z - mu, dw = v[q].w - mu;
            s2 += (dx * dx + dy * dy) + (dz * dz + dw * dw);
        }
        #pragma unroll
        for (int o = 16; o; o >>= 1) s2 += __shfl_xor_sync(0xffffffffu, s2, o);
        const float rinv = rsqrtf(s2 * (1.f / DD) + 1e-5f);
        #pragma unroll
        for (int q = 0; q < 4; q++) {
            acc[q].x += (v[q].x - mu) * rinv * g4[q].x + b4[q].x;
            acc[q].y += (v[q].y - mu) * rinv * g4[q].y + b4[q].y;
            acc[q].z += (v[q].z - mu) * rinv * g4[q].z + b4[q].z;
            acc[q].w += (v[q].w - mu) * rinv * g4[q].w + b4[q].w;
        }
    }
    const float sc = 1.f / NNODE;
    float* zb = zp + b * DD;
    #pragma unroll
    for (int q = 0; q < 4; q++) {
        int f = 4 * (lane + 32 * q);
        atomicAdd(&zb[f + 0], acc[q].x * sc);
        atomicAdd(&zb[f + 1], acc[q].y * sc);
        atomicAdd(&zb[f + 2], acc[q].z * sc);
        atomicAdd(&zb[f + 3], acc[q].w * sc);
    }
}

// ---------------------------------------------------------------------------
__device__ __forceinline__ float block_sum128(float v, float* red, int t)
{
    #pragma unroll
    for (int off = 16; off; off >>= 1) v += __shfl_down_sync(0xffffffffu, v, off);
    if ((t & 31) == 0) red[t >> 5] = v;
    __syncthreads();
    float s = red[0] + red[1] + red[2] + red[3];
    __syncthreads();
    return s;
}

__global__ void classifier_kernel(const float* __restrict__ zp,
                                  const float* __restrict__ Wc1, const float* __restrict__ bc1,
                                  const float* __restrict__ g1,  const float* __restrict__ t1,
                                  const float* __restrict__ Wc2, const float* __restrict__ bc2,
                                  const float* __restrict__ g2,  const float* __restrict__ t2,
                                  const float* __restrict__ Wc3, const float* __restrict__ bc3,
                                  float* __restrict__ logits)
{
    const int b = blockIdx.x;
    const int t = threadIdx.x;
    __shared__ float z[DD];
    __shared__ float h1[128];
    __shared__ float h2[64];
    __shared__ float red[4];

    #pragma unroll
    for (int i = t; i < DD; i += 128) z[i] = zp[b * DD + i];
    __syncthreads();

    float a1 = bc1[t];
    #pragma unroll 8
    for (int k = 0; k < DD; k++) a1 += z[k] * Wc1[k * 128 + t];
    float mu = block_sum128(a1, red, t) * (1.f / 128.f);
    float d0 = a1 - mu;
    float var = block_sum128(d0 * d0, red, t) * (1.f / 128.f);
    h1[t] = fmaxf(d0 * rsqrtf(var + 1e-5f) * g1[t] + t1[t], 0.f);
    __syncthreads();

    float a2 = 0.f;
    if (t < 64) {
        a2 = bc2[t];
        #pragma unroll 8
        for (int k = 0; k < 128; k++) a2 += h1[k] * Wc2[k * 64 + t];
    }
    float c1 = (t < 64) ? a2 : 0.f;
    float mu2 = block_sum128(c1, red, t) * (1.f / 64.f);
    float d2 = a2 - mu2;
    float c2v = (t < 64) ? d2 * d2 : 0.f;
    float var2 = block_sum128(c2v, red, t) * (1.f / 64.f);
    if (t < 64)
        h2[t] = fmaxf(d2 * rsqrtf(var2 + 1e-5f) * g2[t] + t2[t], 0.f);
    __syncthreads();

    if (t < 4) {
        float a3 = bc3[t];
        #pragma unroll
        for (int k = 0; k < 64; k++) a3 += h2[k] * Wc3[k * 4 + t];
        logits[b * 4 + t] = a3;
    }
}

// ---------------------------------------------------------------------------
extern "C" void kernel_launch(void* const* d_in, const int* in_sizes, int n_in,
                              void* d_out, int out_size)
{
    const float* sc  = (const float*)d_in[0];
    const float* W1  = (const float*)d_in[1];
    const float* b1  = (const float*)d_in[2];
    const float* W2  = (const float*)d_in[3];
    const float* b2  = (const float*)d_in[4];
    const float* lng = (const float*)d_in[5];
    const float* lnb = (const float*)d_in[6];
    const float* Wc1 = (const float*)d_in[7];
    const float* bc1 = (const float*)d_in[8];
    const float* g1  = (const float*)d_in[9];
    const float* t1  = (const float*)d_in[10];
    const float* Wc2 = (const float*)d_in[11];
    const float* bc2 = (const float*)d_in[12];
    const float* g2  = (const float*)d_in[13];
    const float* t2  = (const float*)d_in[14];
    const float* Wc3 = (const float*)d_in[15];
    const float* bc3 = (const float*)d_in[16];
    float* out = (float*)d_out;
    float* zp = out + BB * 4;

    __half *Ath, *P, *Qh, *W1t, *W2t;
    float *dis;
    cudaGetSymbolAddress((void**)&Ath, g_Ath);
    cudaGetSymbolAddress((void**)&P,   g_P);
    cudaGetSymbolAddress((void**)&Qh,  g_Qh);
    cudaGetSymbolAddress((void**)&W1t, g_W1t);
    cudaGetSymbolAddress((void**)&W2t, g_W2t);
    cudaGetSymbolAddress((void**)&dis, g_dis);

    cudaFuncSetAttribute(hgemm<true,  true,  false, false, true >,
                         cudaFuncAttributeMaxDynamicSharedMemorySize, SMEM_BYTES);
    cudaFuncSetAttribute(hgemm<false, true,  false, false, true >,
                         cudaFuncAttributeMaxDynamicSharedMemorySize, SMEM_BYTES);
    cudaFuncSetAttribute(hgemm<false, false, true,  true,  true >,
                         cudaFuncAttributeMaxDynamicSharedMemorySize, SMEM_BYTES);
    cudaFuncSetAttribute(hgemm<false, false, false, true,  true >,
                         cudaFuncAttributeMaxDynamicSharedMemorySize, SMEM_BYTES);

    // zero zp (output region) + dis accumulator — every replay, in-graph
    zero2_kernel<<<128, 256>>>(zp, BB * DD, dis, BB * NNODE);

    dim3 tb(32, 8);
    sc_prep<<<dim3(32, 32, BB), tb>>>(sc, Ath, dis);
    rsqrt_fin<<<BB * NNODE / 256, 256>>>(dis);
    w_prep<<<dim3(DD / 32, NNODE / 32), tb>>>(W1, W1t, NNODE, DD);
    w_prep<<<dim3(DD / 32, DD / 32), tb>>>(W2, W2t, DD, DD);

    // G1: P[b][f][j] = h(dis[b,j] * sum_k W1t[f,k]*Ath[b][k,j])  (BTRANS, col-scale)
    hgemm<true, true, false, false, true><<<dim3(NNODE / 128, DD / 128, BB), 256, SMEM_BYTES>>>(
        W1t, Ath, P, dis, nullptr, NNODE, NNODE, NNODE, NNODE,
        0, (size_t)NNODE * NNODE, (size_t)DD * NNODE, NNODE);

    // G2: Qh[b][i][n] = h(relu(dis[b,i]*sum_j Ath[b][i,j]*P[b][n,j] + b1[n]))
    hgemm<false, false, true, true, true><<<dim3(DD / 128, NNODE / 128, BB), 256, SMEM_BYTES>>>(
        Ath, P, Qh, dis, b1, NNODE, NNODE, NNODE, DD,
        (size_t)NNODE * NNODE, (size_t)DD * NNODE, (size_t)NNODE * DD, NNODE);

    // G3: P[b][f][j] = h(dis[b,j] * sum_k W2t[f,k]*Qh[b][j,k])   (col-scale)
    hgemm<false, true, false, false, true><<<dim3(NNODE / 128, DD / 128, BB), 256, SMEM_BYTES>>>(
        W2t, Qh, P, dis, nullptr, DD, DD, DD, NNODE,
        0, (size_t)NNODE * DD, (size_t)DD * NNODE, NNODE);

    // G4: Qh[b][i][n] = h(dis[b,i]*sum_j Ath[b][i,j]*P[b][n,j] + b2[n])  (fp16 H2)
    hgemm<false, false, false, true, true><<<dim3(DD / 128, NNODE / 128, BB), 256, SMEM_BYTES>>>(
        Ath, P, Qh, dis, b2, NNODE, NNODE, NNODE, DD,
        (size_t)NNODE * NNODE, (size_t)DD * NNODE, (size_t)NNODE * DD, NNODE);

    // fused LN + mean-pool over fp16 H2 -> zp, then classifier -> out[0:128)
    ln_pool_kernel<<<dim3(8, BB), 128>>>(Qh, lng, lnb, zp);
    classifier_kernel<<<BB, 128>>>(zp, Wc1, bc1, g1, t1,
                                   Wc2, bc2, g2, t2, Wc3, bc3, out);
}